// round 11
// baseline (speedup 1.0000x reference)
#include <cuda_runtime.h>
#include <cuda_fp16.h>
#include <mma.h>
#include <cstdint>

using namespace nvcuda;

#define N_ROWS 8192
#define K_FEAT 512
#define EPS_TH 1e-10f
#define NSPLIT 4

static __device__ __half g_feats[(size_t)N_ROWS * K_FEAT];           // 8 MB
static __device__ __half g_Sh[(size_t)N_ROWS * N_ROWS];              // 128 MB
static __device__ float  g_part[64][N_ROWS];                         // 2 MB partial row sums
static __device__ float  g_dinv[N_ROWS];
static __device__ float  g_dd[N_ROWS];
static __device__ __half g_Xs[(size_t)N_ROWS * K_FEAT];              // 8 MB
static __device__ float  g_Ypart[NSPLIT][(size_t)N_ROWS * K_FEAT];   // 64 MB

// ---------------------------------------------------------------------------
// cp.async helpers
// ---------------------------------------------------------------------------
__device__ __forceinline__ void cp_async16(void* smem, const void* gmem) {
    unsigned int s = (unsigned int)__cvta_generic_to_shared(smem);
    asm volatile("cp.async.cg.shared.global [%0], [%1], 16;\n" :: "r"(s), "l"(gmem));
}
__device__ __forceinline__ void cp_commit() {
    asm volatile("cp.async.commit_group;\n");
}
__device__ __forceinline__ void cp_wait1() {
    asm volatile("cp.async.wait_group 1;\n");
}
__device__ __forceinline__ void cp_wait0() {
    asm volatile("cp.async.wait_group 0;\n");
}

// ---------------------------------------------------------------------------
// 1. Row L2-normalize X -> fp16 feats
// ---------------------------------------------------------------------------
__global__ void normalize_kernel(const float* __restrict__ X) {
    int row = blockIdx.x;
    const float* x = X + (size_t)row * K_FEAT;
    float s = 0.f;
    for (int k = threadIdx.x; k < K_FEAT; k += 128) {
        float v = x[k];
        s += v * v;
    }
    __shared__ float red[4];
    #pragma unroll
    for (int o = 16; o > 0; o >>= 1) s += __shfl_xor_sync(0xffffffff, s, o);
    if ((threadIdx.x & 31) == 0) red[threadIdx.x >> 5] = s;
    __syncthreads();
    float tot = red[0] + red[1] + red[2] + red[3];
    float inv = 1.0f / fmaxf(sqrtf(tot), 1e-12f);
    __half* f = g_feats + (size_t)row * K_FEAT;
    for (int k = threadIdx.x; k < K_FEAT; k += 128) {
        f[k] = __float2half(x[k] * inv);
    }
}

// ---------------------------------------------------------------------------
// 2. Fused GEMM1 (256 thr, 8 warps x 64x32, 3-stage cp.async single-sync,
//    BK=64). Triangular grid: 2080 CTAs.
// ---------------------------------------------------------------------------
#define BM 128
#define BN 128
#define BK1 64
#define LDA1 72     // halves; 144B rows
#define LDT 132     // float tile leading dim

#define G1_STAGE (2 * BM * LDA1 * 2)       // A+B per stage: 36864 B
#define G1_SMEM  (3 * G1_STAGE)            // 110592 B

__global__ __launch_bounds__(256) void gemm1_fused_kernel() {
    // linear lower-triangle index -> (by, bx), bx >= by, 64 block-cols
    int t = blockIdx.x;
    int by = 0;
    {
        int rem = t;
        while (rem >= 64 - by) { rem -= 64 - by; by++; }
        t = rem;
    }
    const int bx = by + t;

    extern __shared__ char dsm[];
    float (*Tf)[LDT] = (float(*)[LDT])dsm;   // epilogue alias

    const int row0 = by * BM;
    const int col0 = bx * BN;
    const int tid  = threadIdx.x;
    const int lane = tid & 31;
    const int wid  = tid >> 5;
    const int warp_m = wid >> 2;
    const int warp_n = wid & 3;

    const int lr = tid >> 3;
    const int lc = tid & 7;

    wmma::fragment<wmma::accumulator, 16, 16, 16, float> acc[4][2];
    #pragma unroll
    for (int mi = 0; mi < 4; mi++)
        #pragma unroll
        for (int ni = 0; ni < 2; ni++)
            wmma::fill_fragment(acc[mi][ni], 0.0f);

    auto As = [&](int s) { return (__half(*)[LDA1])(dsm + s * G1_STAGE); };
    auto Bs = [&](int s) { return (__half(*)[LDA1])(dsm + s * G1_STAGE + BM * LDA1 * 2); };

    auto load_stage = [&](int s, int k0) {
        __half (*Ab)[LDA1] = As(s);
        __half (*Bb)[LDA1] = Bs(s);
        #pragma unroll
        for (int i = 0; i < 4; i++) {
            int r = lr + i * 32;
            cp_async16(&Ab[r][lc * 8],
                       &g_feats[(size_t)(row0 + r) * K_FEAT + k0 + lc * 8]);
            cp_async16(&Bb[r][lc * 8],
                       &g_feats[(size_t)(col0 + r) * K_FEAT + k0 + lc * 8]);
        }
        cp_commit();
    };

    const int NK = K_FEAT / BK1;   // 8
    load_stage(0, 0);
    load_stage(1, BK1);

    for (int k = 0; k < NK; k++) {
        if (k + 1 < NK) cp_wait1(); else cp_wait0();
        __syncthreads();
        if (k + 2 < NK) load_stage((k + 2) % 3, (k + 2) * BK1);

        __half (*Ab)[LDA1] = As(k % 3);
        __half (*Bb)[LDA1] = Bs(k % 3);
        #pragma unroll
        for (int kk = 0; kk < BK1; kk += 16) {
            wmma::fragment<wmma::matrix_a, 16, 16, 16, half, wmma::row_major> a[4];
            wmma::fragment<wmma::matrix_b, 16, 16, 16, half, wmma::col_major> b[2];
            #pragma unroll
            for (int mi = 0; mi < 4; mi++)
                wmma::load_matrix_sync(a[mi], &Ab[warp_m * 64 + mi * 16][kk], LDA1);
            #pragma unroll
            for (int ni = 0; ni < 2; ni++)
                wmma::load_matrix_sync(b[ni], &Bb[warp_n * 32 + ni * 16][kk], LDA1);
            #pragma unroll
            for (int mi = 0; mi < 4; mi++)
                #pragma unroll
                for (int ni = 0; ni < 2; ni++)
                    wmma::mma_sync(acc[mi][ni], a[mi], b[ni], acc[mi][ni]);
        }
    }
    __syncthreads();   // all MMAs done before aliasing smem

    // ------ epilogue ------
    #pragma unroll
    for (int mi = 0; mi < 4; mi++)
        #pragma unroll
        for (int ni = 0; ni < 2; ni++)
            wmma::store_matrix_sync(
                &Tf[warp_m * 64 + mi * 16][warp_n * 32 + ni * 16],
                acc[mi][ni], LDT, wmma::mem_row_major);
    __syncthreads();

    const bool isdiag = (bx == by);

    #pragma unroll 1
    for (int rr = 0; rr < 16; rr++) {
        int r = wid * 16 + rr;
        float4 v = *(float4*)&Tf[r][lane * 4];
        int c0 = lane * 4;
        float e0 = (v.x < EPS_TH || (isdiag && r == c0 + 0)) ? 0.f : v.x;
        float e1 = (v.y < EPS_TH || (isdiag && r == c0 + 1)) ? 0.f : v.y;
        float e2 = (v.z < EPS_TH || (isdiag && r == c0 + 2)) ? 0.f : v.z;
        float e3 = (v.w < EPS_TH || (isdiag && r == c0 + 3)) ? 0.f : v.w;
        float s = e0 + e1 + e2 + e3;
        #pragma unroll
        for (int o = 16; o > 0; o >>= 1) s += __shfl_xor_sync(0xffffffff, s, o);
        __half2* dst = (__half2*)&g_Sh[(size_t)(row0 + r) * N_ROWS + col0 + c0];
        dst[0] = __floats2half2_rn(e0, e1);
        dst[1] = __floats2half2_rn(e2, e3);
        if (lane == 0) g_part[bx][row0 + r] = s;
    }

    if (!isdiag) {
        #pragma unroll 1
        for (int cc = 0; cc < 16; cc++) {
            int c = wid * 16 + cc;
            float s = 0.f;
            __half h[4];
            #pragma unroll
            for (int j = 0; j < 4; j++) {
                int r = lane + 32 * j;
                float v = Tf[r][c];
                v = (v < EPS_TH) ? 0.f : v;
                s += v;
                h[j] = __float2half(v);
            }
            #pragma unroll
            for (int o = 16; o > 0; o >>= 1) s += __shfl_xor_sync(0xffffffff, s, o);
            size_t base = (size_t)(col0 + c) * N_ROWS + row0;
            #pragma unroll
            for (int j = 0; j < 4; j++)
                g_Sh[base + lane + 32 * j] = h[j];
            if (lane == 0) g_part[by][col0 + c] = s;
        }
    }
}

// ---------------------------------------------------------------------------
// 3. Reduce partials -> d^-1/2, diag term, Xs = d^-1/2 * X (fp16)
// ---------------------------------------------------------------------------
__global__ void scale_kernel(const float* __restrict__ X) {
    const int i = blockIdx.x;
    const int t = threadIdx.x;
    __shared__ float sred[2];
    __shared__ float sdinv;
    float p = (t < 64) ? g_part[t][i] : 0.f;
    #pragma unroll
    for (int o = 16; o > 0; o >>= 1) p += __shfl_xor_sync(0xffffffff, p, o);
    if (t < 64 && (t & 31) == 0) sred[t >> 5] = p;
    __syncthreads();
    if (t == 0) {
        float rs = sred[0] + sred[1] + 1.0f;
        float dinv = rsqrtf(rs);
        g_dinv[i] = dinv;
        g_dd[i] = dinv * dinv;
        sdinv = dinv;
    }
    __syncthreads();
    float dinv = sdinv;
    const float* x = X + (size_t)i * K_FEAT;
    __half* xs = g_Xs + (size_t)i * K_FEAT;
    for (int c = t; c < K_FEAT; c += 128) {
        xs[c] = __float2half(dinv * x[c]);
    }
}

// ---------------------------------------------------------------------------
// 4. GEMM2 (split-K=4, 256 thr, 8 warps x 64x32, 3-stage single-sync, BK=64)
// ---------------------------------------------------------------------------
#define BK2 64
#define LDB2 136    // halves
#define KSPLIT (N_ROWS / NSPLIT)   // 2048

#define G2_ABUF (BM * LDA1 * 2)            // 18432 B
#define G2_BBUF (BK2 * LDB2 * 2)           // 17408 B
#define G2_STAGE (G2_ABUF + G2_BBUF)       // 35840 B
#define G2_SMEM (3 * G2_STAGE)             // 107520 B

__global__ __launch_bounds__(256) void gemm2_kernel() {
    extern __shared__ char dsm[];

    const int row0 = blockIdx.y * BM;
    const int col0 = blockIdx.x * BN;
    const int sk   = blockIdx.z;
    const int kbase = sk * KSPLIT;
    const int tid  = threadIdx.x;
    const int wid  = tid >> 5;
    const int warp_m = wid >> 2;
    const int warp_n = wid & 3;

    const int lrA = tid >> 3, lcA = tid & 7;
    const int lrB = tid >> 4, lcB = tid & 15;

    auto As = [&](int s) { return (__half(*)[LDA1])(dsm + s * G2_STAGE); };
    auto Bs = [&](int s) { return (__half(*)[LDB2])(dsm + s * G2_STAGE + G2_ABUF); };

    wmma::fragment<wmma::accumulator, 16, 16, 16, float> acc[4][2];
    #pragma unroll
    for (int mi = 0; mi < 4; mi++)
        #pragma unroll
        for (int ni = 0; ni < 2; ni++)
            wmma::fill_fragment(acc[mi][ni], 0.0f);

    auto load_stage = [&](int s, int k0) {
        __half (*Ab)[LDA1] = As(s);
        __half (*Bb)[LDB2] = Bs(s);
        #pragma unroll
        for (int i = 0; i < 4; i++) {
            int r = lrA + i * 32;
            cp_async16(&Ab[r][lcA * 8],
                       &g_Sh[(size_t)(row0 + r) * N_ROWS + k0 + lcA * 8]);
        }
        #pragma unroll
        for (int i = 0; i < 4; i++) {
            int r = lrB + i * 16;
            cp_async16(&Bb[r][lcB * 8],
                       &g_Xs[(size_t)(k0 + r) * K_FEAT + col0 + lcB * 8]);
        }
        cp_commit();
    };

    const int NK = KSPLIT / BK2;   // 32
    load_stage(0, kbase);
    load_stage(1, kbase + BK2);

    for (int k = 0; k < NK; k++) {
        if (k + 1 < NK) cp_wait1(); else cp_wait0();
        __syncthreads();
        if (k + 2 < NK) load_stage((k + 2) % 3, kbase + (k + 2) * BK2);

        __half (*Ab)[LDA1] = As(k % 3);
        __half (*Bb)[LDB2] = Bs(k % 3);
        #pragma unroll
        for (int kk = 0; kk < BK2; kk += 16) {
            wmma::fragment<wmma::matrix_a, 16, 16, 16, half, wmma::row_major> a[4];
            wmma::fragment<wmma::matrix_b, 16, 16, 16, half, wmma::row_major> b[2];
            #pragma unroll
            for (int mi = 0; mi < 4; mi++)
                wmma::load_matrix_sync(a[mi], &Ab[warp_m * 64 + mi * 16][kk], LDA1);
            #pragma unroll
            for (int ni = 0; ni < 2; ni++)
                wmma::load_matrix_sync(b[ni], &Bb[kk][warp_n * 32 + ni * 16], LDB2);
            #pragma unroll
            for (int mi = 0; mi < 4; mi++)
                #pragma unroll
                for (int ni = 0; ni < 2; ni++)
                    wmma::mma_sync(acc[mi][ni], a[mi], b[ni], acc[mi][ni]);
        }
    }

    float* yp = g_Ypart[sk];
    #pragma unroll
    for (int mi = 0; mi < 4; mi++)
        #pragma unroll
        for (int ni = 0; ni < 2; ni++)
            wmma::store_matrix_sync(
                &yp[(size_t)(row0 + warp_m * 64 + mi * 16) * K_FEAT +
                    (col0 + warp_n * 32 + ni * 16)],
                acc[mi][ni], K_FEAT, wmma::mem_row_major);
}

// ---------------------------------------------------------------------------
// 5. Epilogue: out = (1/3) X + (2/3) (dinv_i * sum(Ypart) + dd_i * X)
// ---------------------------------------------------------------------------
__global__ void epilogue_kernel(const float* __restrict__ X, float* __restrict__ out) {
    const float REG = 2.0f / 3.0f;
    int idx = blockIdx.x * 256 + threadIdx.x;
    int i = idx >> 9;
    float x = X[idx];
    float y = g_Ypart[0][idx] + g_Ypart[1][idx] + g_Ypart[2][idx] + g_Ypart[3][idx];
    out[idx] = (1.0f - REG) * x + REG * (g_dinv[i] * y + g_dd[i] * x);
}

// ---------------------------------------------------------------------------
extern "C" void kernel_launch(void* const* d_in, const int* in_sizes, int n_in,
                              void* d_out, int out_size) {
    const float* X = (const float*)d_in[0];
    float* out = (float*)d_out;

    cudaFuncSetAttribute(gemm1_fused_kernel,
                         cudaFuncAttributeMaxDynamicSharedMemorySize, G1_SMEM);
    cudaFuncSetAttribute(gemm2_kernel,
                         cudaFuncAttributeMaxDynamicSharedMemorySize, G2_SMEM);

    normalize_kernel<<<N_ROWS, 128>>>(X);

    gemm1_fused_kernel<<<2080, 256, G1_SMEM>>>();   // triangular grid

    scale_kernel<<<N_ROWS, 128>>>(X);

    dim3 g2(K_FEAT / BN, N_ROWS / BM, NSPLIT);   // 4 x 64 x 4 = 1024 CTAs
    gemm2_kernel<<<g2, 256, G2_SMEM>>>();

    epilogue_kernel<<<(N_ROWS * K_FEAT) / 256, 256>>>(X, out);
}

// round 15
// speedup vs baseline: 1.0558x; 1.0558x over previous
#include <cuda_runtime.h>
#include <cuda_fp16.h>
#include <mma.h>
#include <cstdint>

using namespace nvcuda;

#define N_ROWS 8192
#define K_FEAT 512
#define EPS_TH 1e-10f
#define NSPLIT 4

static __device__ __half g_feats[(size_t)N_ROWS * K_FEAT];           // 8 MB
static __device__ __half g_Sh[(size_t)N_ROWS * N_ROWS];              // 128 MB
static __device__ float  g_part[64][N_ROWS];                         // 2 MB partial row sums
static __device__ float  g_dinv[N_ROWS];
static __device__ float  g_dd[N_ROWS];
static __device__ __half g_Xs[(size_t)N_ROWS * K_FEAT];              // 8 MB
static __device__ __half g_Ypart[NSPLIT][(size_t)N_ROWS * K_FEAT];   // 32 MB

// ---------------------------------------------------------------------------
// cp.async helpers
// ---------------------------------------------------------------------------
__device__ __forceinline__ void cp_async16(void* smem, const void* gmem) {
    unsigned int s = (unsigned int)__cvta_generic_to_shared(smem);
    asm volatile("cp.async.cg.shared.global [%0], [%1], 16;\n" :: "r"(s), "l"(gmem));
}
__device__ __forceinline__ void cp_commit() {
    asm volatile("cp.async.commit_group;\n");
}
__device__ __forceinline__ void cp_wait1() {
    asm volatile("cp.async.wait_group 1;\n");
}
__device__ __forceinline__ void cp_wait0() {
    asm volatile("cp.async.wait_group 0;\n");
}

// ---------------------------------------------------------------------------
// 1. Row L2-normalize X -> fp16 feats
// ---------------------------------------------------------------------------
__global__ void normalize_kernel(const float* __restrict__ X) {
    int row = blockIdx.x;
    const float* x = X + (size_t)row * K_FEAT;
    float s = 0.f;
    for (int k = threadIdx.x; k < K_FEAT; k += 128) {
        float v = x[k];
        s += v * v;
    }
    __shared__ float red[4];
    #pragma unroll
    for (int o = 16; o > 0; o >>= 1) s += __shfl_xor_sync(0xffffffff, s, o);
    if ((threadIdx.x & 31) == 0) red[threadIdx.x >> 5] = s;
    __syncthreads();
    float tot = red[0] + red[1] + red[2] + red[3];
    float inv = 1.0f / fmaxf(sqrtf(tot), 1e-12f);
    __half* f = g_feats + (size_t)row * K_FEAT;
    for (int k = threadIdx.x; k < K_FEAT; k += 128) {
        f[k] = __float2half(x[k] * inv);
    }
}

// ---------------------------------------------------------------------------
// 2. Fused GEMM1 (256 thr, 8 warps x 64x32, 2-stage cp.async, BK=64,
//    fp16 accumulators). Triangular grid: 2080 CTAs.
// ---------------------------------------------------------------------------
#define BM 128
#define BN 128
#define BK1 64
#define LDA1 72     // halves; 144B rows
#define LDTH 136    // half tile leading dim (272B rows, 16B-mult)

#define G1_ABUF (BM * LDA1 * 2)            // 18432 B per buffer
#define G1_SMEM (4 * G1_ABUF)              // 73728 B total

__global__ __launch_bounds__(256) void gemm1_fused_kernel() {
    // linear lower-triangle index -> (by, bx), bx >= by, 64 block-cols
    int t = blockIdx.x;
    int by = 0;
    {
        int rem = t;
        while (rem >= 64 - by) { rem -= 64 - by; by++; }
        t = rem;
    }
    const int bx = by + t;

    extern __shared__ char dsm[];
    __half (*Tf)[LDTH] = (__half(*)[LDTH])dsm;   // epilogue alias (34816 B)

    const int row0 = by * BM;
    const int col0 = bx * BN;
    const int tid  = threadIdx.x;
    const int lane = tid & 31;
    const int wid  = tid >> 5;
    const int warp_m = wid >> 2;
    const int warp_n = wid & 3;

    const int lr = tid >> 3;
    const int lc = tid & 7;

    wmma::fragment<wmma::accumulator, 16, 16, 16, half> acc[4][2];
    #pragma unroll
    for (int mi = 0; mi < 4; mi++)
        #pragma unroll
        for (int ni = 0; ni < 2; ni++)
            wmma::fill_fragment(acc[mi][ni], __float2half(0.0f));

    auto As = [&](int b) { return (__half(*)[LDA1])(dsm + b * G1_ABUF); };
    auto Bs = [&](int b) { return (__half(*)[LDA1])(dsm + 2 * G1_ABUF + b * G1_ABUF); };

    auto load_stage = [&](int buf, int k0) {
        __half (*Ab)[LDA1] = As(buf);
        __half (*Bb)[LDA1] = Bs(buf);
        #pragma unroll
        for (int i = 0; i < 4; i++) {
            int r = lr + i * 32;
            cp_async16(&Ab[r][lc * 8],
                       &g_feats[(size_t)(row0 + r) * K_FEAT + k0 + lc * 8]);
            cp_async16(&Bb[r][lc * 8],
                       &g_feats[(size_t)(col0 + r) * K_FEAT + k0 + lc * 8]);
        }
        cp_commit();
    };

    const int NK = K_FEAT / BK1;   // 8
    load_stage(0, 0);

    for (int k = 0; k < NK; k++) {
        if (k + 1 < NK) { load_stage((k + 1) & 1, (k + 1) * BK1); cp_wait1(); }
        else            { cp_wait0(); }
        __syncthreads();

        __half (*Ab)[LDA1] = As(k & 1);
        __half (*Bb)[LDA1] = Bs(k & 1);
        #pragma unroll
        for (int kk = 0; kk < BK1; kk += 16) {
            wmma::fragment<wmma::matrix_a, 16, 16, 16, half, wmma::row_major> a[4];
            wmma::fragment<wmma::matrix_b, 16, 16, 16, half, wmma::col_major> b[2];
            #pragma unroll
            for (int mi = 0; mi < 4; mi++)
                wmma::load_matrix_sync(a[mi], &Ab[warp_m * 64 + mi * 16][kk], LDA1);
            #pragma unroll
            for (int ni = 0; ni < 2; ni++)
                wmma::load_matrix_sync(b[ni], &Bb[warp_n * 32 + ni * 16][kk], LDA1);
            #pragma unroll
            for (int mi = 0; mi < 4; mi++)
                #pragma unroll
                for (int ni = 0; ni < 2; ni++)
                    wmma::mma_sync(acc[mi][ni], a[mi], b[ni], acc[mi][ni]);
        }
        __syncthreads();
    }

    // ------ epilogue ------
    #pragma unroll
    for (int mi = 0; mi < 4; mi++)
        #pragma unroll
        for (int ni = 0; ni < 2; ni++)
            wmma::store_matrix_sync(
                &Tf[warp_m * 64 + mi * 16][warp_n * 32 + ni * 16],
                acc[mi][ni], LDTH, wmma::mem_row_major);
    __syncthreads();

    const bool isdiag = (bx == by);

    // Direct pass: warp w handles rows w*16..w*16+15; lane -> 4 cols.
    #pragma unroll 1
    for (int rr = 0; rr < 16; rr++) {
        int r = wid * 16 + rr;
        int c0 = lane * 4;
        uint2 raw = *(uint2*)&Tf[r][c0];
        __half2 p0 = *(__half2*)&raw.x;
        __half2 p1 = *(__half2*)&raw.y;
        float v0 = __low2float(p0),  v1 = __high2float(p0);
        float v2 = __low2float(p1),  v3 = __high2float(p1);
        float e0 = (v0 < EPS_TH || (isdiag && r == c0 + 0)) ? 0.f : v0;
        float e1 = (v1 < EPS_TH || (isdiag && r == c0 + 1)) ? 0.f : v1;
        float e2 = (v2 < EPS_TH || (isdiag && r == c0 + 2)) ? 0.f : v2;
        float e3 = (v3 < EPS_TH || (isdiag && r == c0 + 3)) ? 0.f : v3;
        float s = e0 + e1 + e2 + e3;
        #pragma unroll
        for (int o = 16; o > 0; o >>= 1) s += __shfl_xor_sync(0xffffffff, s, o);
        __half2* dst = (__half2*)&g_Sh[(size_t)(row0 + r) * N_ROWS + col0 + c0];
        dst[0] = __floats2half2_rn(e0, e1);
        dst[1] = __floats2half2_rn(e2, e3);
        if (lane == 0) g_part[bx][row0 + r] = s;
    }

    // Transposed pass (off-diag blocks): warp w -> cols w*16..w*16+15.
    if (!isdiag) {
        #pragma unroll 1
        for (int cc = 0; cc < 16; cc++) {
            int c = wid * 16 + cc;
            float s = 0.f;
            __half h[4];
            #pragma unroll
            for (int j = 0; j < 4; j++) {
                int r = lane + 32 * j;
                float v = __half2float(Tf[r][c]);
                v = (v < EPS_TH) ? 0.f : v;
                s += v;
                h[j] = __float2half(v);
            }
            #pragma unroll
            for (int o = 16; o > 0; o >>= 1) s += __shfl_xor_sync(0xffffffff, s, o);
            size_t base = (size_t)(col0 + c) * N_ROWS + row0;
            #pragma unroll
            for (int j = 0; j < 4; j++)
                g_Sh[base + lane + 32 * j] = h[j];
            if (lane == 0) g_part[by][col0 + c] = s;
        }
    }
}

// ---------------------------------------------------------------------------
// 3. Reduce partials -> d^-1/2, diag term, Xs = d^-1/2 * X (fp16)
// ---------------------------------------------------------------------------
__global__ void scale_kernel(const float* __restrict__ X) {
    const int i = blockIdx.x;
    const int t = threadIdx.x;
    __shared__ float sred[2];
    __shared__ float sdinv;
    float p = (t < 64) ? g_part[t][i] : 0.f;
    #pragma unroll
    for (int o = 16; o > 0; o >>= 1) p += __shfl_xor_sync(0xffffffff, p, o);
    if (t < 64 && (t & 31) == 0) sred[t >> 5] = p;
    __syncthreads();
    if (t == 0) {
        float rs = sred[0] + sred[1] + 1.0f;
        float dinv = rsqrtf(rs);
        g_dinv[i] = dinv;
        g_dd[i] = dinv * dinv;
        sdinv = dinv;
    }
    __syncthreads();
    float dinv = sdinv;
    const float* x = X + (size_t)i * K_FEAT;
    __half* xs = g_Xs + (size_t)i * K_FEAT;
    for (int c = t; c < K_FEAT; c += 128) {
        xs[c] = __float2half(dinv * x[c]);
    }
}

// ---------------------------------------------------------------------------
// 4. GEMM2 (split-K=4, 256 thr, 8 warps x 64x32, 2-stage, BK=64,
//    fp16 accumulators)
// ---------------------------------------------------------------------------
#define BK2 64
#define LDB2 136    // halves
#define KSPLIT (N_ROWS / NSPLIT)   // 2048

#define G2_ABUF (BM * LDA1 * 2)            // 18432 B
#define G2_BBUF (BK2 * LDB2 * 2)           // 17408 B
#define G2_SMEM (2 * G2_ABUF + 2 * G2_BBUF)  // 71680 B

__global__ __launch_bounds__(256) void gemm2_kernel() {
    extern __shared__ char dsm[];

    const int row0 = blockIdx.y * BM;
    const int col0 = blockIdx.x * BN;
    const int sk   = blockIdx.z;
    const int kbase = sk * KSPLIT;
    const int tid  = threadIdx.x;
    const int wid  = tid >> 5;
    const int warp_m = wid >> 2;
    const int warp_n = wid & 3;

    const int lrA = tid >> 3, lcA = tid & 7;
    const int lrB = tid >> 4, lcB = tid & 15;

    auto As = [&](int b) { return (__half(*)[LDA1])(dsm + b * G2_ABUF); };
    auto Bs = [&](int b) { return (__half(*)[LDB2])(dsm + 2 * G2_ABUF + b * G2_BBUF); };

    wmma::fragment<wmma::accumulator, 16, 16, 16, half> acc[4][2];
    #pragma unroll
    for (int mi = 0; mi < 4; mi++)
        #pragma unroll
        for (int ni = 0; ni < 2; ni++)
            wmma::fill_fragment(acc[mi][ni], __float2half(0.0f));

    auto load_stage = [&](int buf, int k0) {
        __half (*Ab)[LDA1] = As(buf);
        __half (*Bb)[LDB2] = Bs(buf);
        #pragma unroll
        for (int i = 0; i < 4; i++) {
            int r = lrA + i * 32;
            cp_async16(&Ab[r][lcA * 8],
                       &g_Sh[(size_t)(row0 + r) * N_ROWS + k0 + lcA * 8]);
        }
        #pragma unroll
        for (int i = 0; i < 4; i++) {
            int r = lrB + i * 16;
            cp_async16(&Bb[r][lcB * 8],
                       &g_Xs[(size_t)(k0 + r) * K_FEAT + col0 + lcB * 8]);
        }
        cp_commit();
    };

    const int NK = KSPLIT / BK2;   // 32
    load_stage(0, kbase);

    for (int k = 0; k < NK; k++) {
        if (k + 1 < NK) { load_stage((k + 1) & 1, kbase + (k + 1) * BK2); cp_wait1(); }
        else            { cp_wait0(); }
        __syncthreads();

        __half (*Ab)[LDA1] = As(k & 1);
        __half (*Bb)[LDB2] = Bs(k & 1);
        #pragma unroll
        for (int kk = 0; kk < BK2; kk += 16) {
            wmma::fragment<wmma::matrix_a, 16, 16, 16, half, wmma::row_major> a[4];
            wmma::fragment<wmma::matrix_b, 16, 16, 16, half, wmma::row_major> b[2];
            #pragma unroll
            for (int mi = 0; mi < 4; mi++)
                wmma::load_matrix_sync(a[mi], &Ab[warp_m * 64 + mi * 16][kk], LDA1);
            #pragma unroll
            for (int ni = 0; ni < 2; ni++)
                wmma::load_matrix_sync(b[ni], &Bb[kk][warp_n * 32 + ni * 16], LDB2);
            #pragma unroll
            for (int mi = 0; mi < 4; mi++)
                #pragma unroll
                for (int ni = 0; ni < 2; ni++)
                    wmma::mma_sync(acc[mi][ni], a[mi], b[ni], acc[mi][ni]);
        }
        __syncthreads();
    }

    __half* yp = g_Ypart[sk];
    #pragma unroll
    for (int mi = 0; mi < 4; mi++)
        #pragma unroll
        for (int ni = 0; ni < 2; ni++)
            wmma::store_matrix_sync(
                &yp[(size_t)(row0 + warp_m * 64 + mi * 16) * K_FEAT +
                    (col0 + warp_n * 32 + ni * 16)],
                acc[mi][ni], K_FEAT, wmma::mem_row_major);
}

// ---------------------------------------------------------------------------
// 5. Epilogue: out = (1/3) X + (2/3) (dinv_i * sum(Ypart) + dd_i * X)
// ---------------------------------------------------------------------------
__global__ void epilogue_kernel(const float* __restrict__ X, float* __restrict__ out) {
    const float REG = 2.0f / 3.0f;
    int idx = blockIdx.x * 256 + threadIdx.x;
    int i = idx >> 9;
    float x = X[idx];
    float y = __half2float(g_Ypart[0][idx]) + __half2float(g_Ypart[1][idx])
            + __half2float(g_Ypart[2][idx]) + __half2float(g_Ypart[3][idx]);
    out[idx] = (1.0f - REG) * x + REG * (g_dinv[i] * y + g_dd[i] * x);
}

// ---------------------------------------------------------------------------
extern "C" void kernel_launch(void* const* d_in, const int* in_sizes, int n_in,
                              void* d_out, int out_size) {
    const float* X = (const float*)d_in[0];
    float* out = (float*)d_out;

    cudaFuncSetAttribute(gemm1_fused_kernel,
                         cudaFuncAttributeMaxDynamicSharedMemorySize, G1_SMEM);
    cudaFuncSetAttribute(gemm2_kernel,
                         cudaFuncAttributeMaxDynamicSharedMemorySize, G2_SMEM);

    normalize_kernel<<<N_ROWS, 128>>>(X);

    gemm1_fused_kernel<<<2080, 256, G1_SMEM>>>();   // triangular grid

    scale_kernel<<<N_ROWS, 128>>>(X);

    dim3 g2(K_FEAT / BN, N_ROWS / BM, NSPLIT);   // 4 x 64 x 4 = 1024 CTAs
    gemm2_kernel<<<g2, 256, G2_SMEM>>>();

    epilogue_kernel<<<(N_ROWS * K_FEAT) / 256, 256>>>(X, out);
}

// round 17
// speedup vs baseline: 1.1039x; 1.0455x over previous
#include <cuda_runtime.h>
#include <cuda_fp16.h>
#include <mma.h>
#include <cstdint>

using namespace nvcuda;

#define N_ROWS 8192
#define K_FEAT 512
#define EPS_TH 1e-10f
#define NSPLIT 4

static __device__ __half g_feats[(size_t)N_ROWS * K_FEAT];           // 8 MB
static __device__ __half g_Sh[(size_t)N_ROWS * N_ROWS];              // 128 MB
static __device__ float  g_part[64][N_ROWS];                         // 2 MB partial row sums
static __device__ float  g_dinv[N_ROWS];
static __device__ float  g_dd[N_ROWS];
static __device__ __half g_Xs[(size_t)N_ROWS * K_FEAT];              // 8 MB
static __device__ __half g_Ypart[NSPLIT][(size_t)N_ROWS * K_FEAT];   // 32 MB

// ---------------------------------------------------------------------------
// cp.async helpers
// ---------------------------------------------------------------------------
__device__ __forceinline__ void cp_async16(void* smem, const void* gmem) {
    unsigned int s = (unsigned int)__cvta_generic_to_shared(smem);
    asm volatile("cp.async.cg.shared.global [%0], [%1], 16;\n" :: "r"(s), "l"(gmem));
}
__device__ __forceinline__ void cp_commit() {
    asm volatile("cp.async.commit_group;\n");
}
__device__ __forceinline__ void cp_wait1() {
    asm volatile("cp.async.wait_group 1;\n");
}
__device__ __forceinline__ void cp_wait0() {
    asm volatile("cp.async.wait_group 0;\n");
}

// ---------------------------------------------------------------------------
// 1. Row L2-normalize X -> fp16 feats
// ---------------------------------------------------------------------------
__global__ void normalize_kernel(const float* __restrict__ X) {
    int row = blockIdx.x;
    const float* x = X + (size_t)row * K_FEAT;
    float s = 0.f;
    for (int k = threadIdx.x; k < K_FEAT; k += 128) {
        float v = x[k];
        s += v * v;
    }
    __shared__ float red[4];
    #pragma unroll
    for (int o = 16; o > 0; o >>= 1) s += __shfl_xor_sync(0xffffffff, s, o);
    if ((threadIdx.x & 31) == 0) red[threadIdx.x >> 5] = s;
    __syncthreads();
    float tot = red[0] + red[1] + red[2] + red[3];
    float inv = 1.0f / fmaxf(sqrtf(tot), 1e-12f);
    __half* f = g_feats + (size_t)row * K_FEAT;
    for (int k = threadIdx.x; k < K_FEAT; k += 128) {
        f[k] = __float2half(x[k] * inv);
    }
}

// ---------------------------------------------------------------------------
// 2. Fused GEMM1 (256 thr, 8 warps x 64x32, 2-stage cp.async, BK=64,
//    fp16 accumulators). Triangular grid: 2080 CTAs. (unchanged from R15)
// ---------------------------------------------------------------------------
#define BM 128
#define BN 128
#define BK1 64
#define LDA1 72     // halves; 144B rows
#define LDTH 136    // half tile leading dim (272B rows, 16B-mult)

#define G1_ABUF (BM * LDA1 * 2)            // 18432 B per buffer
#define G1_SMEM (4 * G1_ABUF)              // 73728 B total

__global__ __launch_bounds__(256) void gemm1_fused_kernel() {
    // linear lower-triangle index -> (by, bx), bx >= by, 64 block-cols
    int t = blockIdx.x;
    int by = 0;
    {
        int rem = t;
        while (rem >= 64 - by) { rem -= 64 - by; by++; }
        t = rem;
    }
    const int bx = by + t;

    extern __shared__ char dsm[];
    __half (*Tf)[LDTH] = (__half(*)[LDTH])dsm;   // epilogue alias (34816 B)

    const int row0 = by * BM;
    const int col0 = bx * BN;
    const int tid  = threadIdx.x;
    const int lane = tid & 31;
    const int wid  = tid >> 5;
    const int warp_m = wid >> 2;
    const int warp_n = wid & 3;

    const int lr = tid >> 3;
    const int lc = tid & 7;

    wmma::fragment<wmma::accumulator, 16, 16, 16, half> acc[4][2];
    #pragma unroll
    for (int mi = 0; mi < 4; mi++)
        #pragma unroll
        for (int ni = 0; ni < 2; ni++)
            wmma::fill_fragment(acc[mi][ni], __float2half(0.0f));

    auto As = [&](int b) { return (__half(*)[LDA1])(dsm + b * G1_ABUF); };
    auto Bs = [&](int b) { return (__half(*)[LDA1])(dsm + 2 * G1_ABUF + b * G1_ABUF); };

    auto load_stage = [&](int buf, int k0) {
        __half (*Ab)[LDA1] = As(buf);
        __half (*Bb)[LDA1] = Bs(buf);
        #pragma unroll
        for (int i = 0; i < 4; i++) {
            int r = lr + i * 32;
            cp_async16(&Ab[r][lc * 8],
                       &g_feats[(size_t)(row0 + r) * K_FEAT + k0 + lc * 8]);
            cp_async16(&Bb[r][lc * 8],
                       &g_feats[(size_t)(col0 + r) * K_FEAT + k0 + lc * 8]);
        }
        cp_commit();
    };

    const int NK = K_FEAT / BK1;   // 8
    load_stage(0, 0);

    for (int k = 0; k < NK; k++) {
        if (k + 1 < NK) { load_stage((k + 1) & 1, (k + 1) * BK1); cp_wait1(); }
        else            { cp_wait0(); }
        __syncthreads();

        __half (*Ab)[LDA1] = As(k & 1);
        __half (*Bb)[LDA1] = Bs(k & 1);
        #pragma unroll
        for (int kk = 0; kk < BK1; kk += 16) {
            wmma::fragment<wmma::matrix_a, 16, 16, 16, half, wmma::row_major> a[4];
            wmma::fragment<wmma::matrix_b, 16, 16, 16, half, wmma::col_major> b[2];
            #pragma unroll
            for (int mi = 0; mi < 4; mi++)
                wmma::load_matrix_sync(a[mi], &Ab[warp_m * 64 + mi * 16][kk], LDA1);
            #pragma unroll
            for (int ni = 0; ni < 2; ni++)
                wmma::load_matrix_sync(b[ni], &Bb[warp_n * 32 + ni * 16][kk], LDA1);
            #pragma unroll
            for (int mi = 0; mi < 4; mi++)
                #pragma unroll
                for (int ni = 0; ni < 2; ni++)
                    wmma::mma_sync(acc[mi][ni], a[mi], b[ni], acc[mi][ni]);
        }
        __syncthreads();
    }

    // ------ epilogue ------
    #pragma unroll
    for (int mi = 0; mi < 4; mi++)
        #pragma unroll
        for (int ni = 0; ni < 2; ni++)
            wmma::store_matrix_sync(
                &Tf[warp_m * 64 + mi * 16][warp_n * 32 + ni * 16],
                acc[mi][ni], LDTH, wmma::mem_row_major);
    __syncthreads();

    const bool isdiag = (bx == by);

    // Direct pass: warp w handles rows w*16..w*16+15; lane -> 4 cols.
    #pragma unroll 1
    for (int rr = 0; rr < 16; rr++) {
        int r = wid * 16 + rr;
        int c0 = lane * 4;
        uint2 raw = *(uint2*)&Tf[r][c0];
        __half2 p0 = *(__half2*)&raw.x;
        __half2 p1 = *(__half2*)&raw.y;
        float v0 = __low2float(p0),  v1 = __high2float(p0);
        float v2 = __low2float(p1),  v3 = __high2float(p1);
        float e0 = (v0 < EPS_TH || (isdiag && r == c0 + 0)) ? 0.f : v0;
        float e1 = (v1 < EPS_TH || (isdiag && r == c0 + 1)) ? 0.f : v1;
        float e2 = (v2 < EPS_TH || (isdiag && r == c0 + 2)) ? 0.f : v2;
        float e3 = (v3 < EPS_TH || (isdiag && r == c0 + 3)) ? 0.f : v3;
        float s = e0 + e1 + e2 + e3;
        #pragma unroll
        for (int o = 16; o > 0; o >>= 1) s += __shfl_xor_sync(0xffffffff, s, o);
        __half2* dst = (__half2*)&g_Sh[(size_t)(row0 + r) * N_ROWS + col0 + c0];
        dst[0] = __floats2half2_rn(e0, e1);
        dst[1] = __floats2half2_rn(e2, e3);
        if (lane == 0) g_part[bx][row0 + r] = s;
    }

    // Transposed pass (off-diag blocks): warp w -> cols w*16..w*16+15.
    if (!isdiag) {
        #pragma unroll 1
        for (int cc = 0; cc < 16; cc++) {
            int c = wid * 16 + cc;
            float s = 0.f;
            __half h[4];
            #pragma unroll
            for (int j = 0; j < 4; j++) {
                int r = lane + 32 * j;
                float v = __half2float(Tf[r][c]);
                v = (v < EPS_TH) ? 0.f : v;
                s += v;
                h[j] = __float2half(v);
            }
            #pragma unroll
            for (int o = 16; o > 0; o >>= 1) s += __shfl_xor_sync(0xffffffff, s, o);
            size_t base = (size_t)(col0 + c) * N_ROWS + row0;
            #pragma unroll
            for (int j = 0; j < 4; j++)
                g_Sh[base + lane + 32 * j] = h[j];
            if (lane == 0) g_part[by][col0 + c] = s;
        }
    }
}

// ---------------------------------------------------------------------------
// 3. Reduce partials -> d^-1/2, diag term, Xs = d^-1/2 * X (fp16)
// ---------------------------------------------------------------------------
__global__ void scale_kernel(const float* __restrict__ X) {
    const int i = blockIdx.x;
    const int t = threadIdx.x;
    __shared__ float sred[2];
    __shared__ float sdinv;
    float p = (t < 64) ? g_part[t][i] : 0.f;
    #pragma unroll
    for (int o = 16; o > 0; o >>= 1) p += __shfl_xor_sync(0xffffffff, p, o);
    if (t < 64 && (t & 31) == 0) sred[t >> 5] = p;
    __syncthreads();
    if (t == 0) {
        float rs = sred[0] + sred[1] + 1.0f;
        float dinv = rsqrtf(rs);
        g_dinv[i] = dinv;
        g_dd[i] = dinv * dinv;
        sdinv = dinv;
    }
    __syncthreads();
    float dinv = sdinv;
    const float* x = X + (size_t)i * K_FEAT;
    __half* xs = g_Xs + (size_t)i * K_FEAT;
    for (int c = t; c < K_FEAT; c += 128) {
        xs[c] = __float2half(dinv * x[c]);
    }
}

// ---------------------------------------------------------------------------
// 4. GEMM2 (split-K=4, 128 thr, 4 warps x 64x64, 2-stage, BK=64,
//    fp16 accumulators). 2x MMA per fragment-load vs 64x32 tiles.
// ---------------------------------------------------------------------------
#define BK2 64
#define LDB2 136    // halves
#define KSPLIT (N_ROWS / NSPLIT)   // 2048

#define G2_ABUF (BM * LDA1 * 2)            // 18432 B
#define G2_BBUF (BK2 * LDB2 * 2)           // 17408 B
#define G2_SMEM (2 * G2_ABUF + 2 * G2_BBUF)  // 71680 B

__global__ __launch_bounds__(128) void gemm2_kernel() {
    extern __shared__ char dsm[];

    const int row0 = blockIdx.y * BM;
    const int col0 = blockIdx.x * BN;
    const int sk   = blockIdx.z;
    const int kbase = sk * KSPLIT;
    const int tid  = threadIdx.x;
    const int wid  = tid >> 5;
    const int warp_m = wid >> 1;   // 0..1 (64 rows each)
    const int warp_n = wid & 1;    // 0..1 (64 cols each)

    const int lrA = tid >> 3, lcA = tid & 7;      // A: 16 row-groups x 8 chunks
    const int lrB = tid >> 4, lcB = tid & 15;     // B: 8 row-groups x 16 chunks

    auto As = [&](int b) { return (__half(*)[LDA1])(dsm + b * G2_ABUF); };
    auto Bs = [&](int b) { return (__half(*)[LDB2])(dsm + 2 * G2_ABUF + b * G2_BBUF); };

    wmma::fragment<wmma::accumulator, 16, 16, 16, half> acc[4][4];
    #pragma unroll
    for (int mi = 0; mi < 4; mi++)
        #pragma unroll
        for (int ni = 0; ni < 4; ni++)
            wmma::fill_fragment(acc[mi][ni], __float2half(0.0f));

    auto load_stage = [&](int buf, int k0) {
        __half (*Ab)[LDA1] = As(buf);
        __half (*Bb)[LDB2] = Bs(buf);
        #pragma unroll
        for (int i = 0; i < 8; i++) {
            int r = lrA + i * 16;
            cp_async16(&Ab[r][lcA * 8],
                       &g_Sh[(size_t)(row0 + r) * N_ROWS + k0 + lcA * 8]);
        }
        #pragma unroll
        for (int i = 0; i < 8; i++) {
            int r = lrB + i * 8;
            cp_async16(&Bb[r][lcB * 8],
                       &g_Xs[(size_t)(k0 + r) * K_FEAT + col0 + lcB * 8]);
        }
        cp_commit();
    };

    const int NK = KSPLIT / BK2;   // 32
    load_stage(0, kbase);

    for (int k = 0; k < NK; k++) {
        if (k + 1 < NK) { load_stage((k + 1) & 1, kbase + (k + 1) * BK2); cp_wait1(); }
        else            { cp_wait0(); }
        __syncthreads();

        __half (*Ab)[LDA1] = As(k & 1);
        __half (*Bb)[LDB2] = Bs(k & 1);
        #pragma unroll
        for (int kk = 0; kk < BK2; kk += 16) {
            wmma::fragment<wmma::matrix_a, 16, 16, 16, half, wmma::row_major> a[4];
            wmma::fragment<wmma::matrix_b, 16, 16, 16, half, wmma::row_major> b[4];
            #pragma unroll
            for (int mi = 0; mi < 4; mi++)
                wmma::load_matrix_sync(a[mi], &Ab[warp_m * 64 + mi * 16][kk], LDA1);
            #pragma unroll
            for (int ni = 0; ni < 4; ni++)
                wmma::load_matrix_sync(b[ni], &Bb[kk][warp_n * 64 + ni * 16], LDB2);
            #pragma unroll
            for (int mi = 0; mi < 4; mi++)
                #pragma unroll
                for (int ni = 0; ni < 4; ni++)
                    wmma::mma_sync(acc[mi][ni], a[mi], b[ni], acc[mi][ni]);
        }
        __syncthreads();
    }

    __half* yp = g_Ypart[sk];
    #pragma unroll
    for (int mi = 0; mi < 4; mi++)
        #pragma unroll
        for (int ni = 0; ni < 4; ni++)
            wmma::store_matrix_sync(
                &yp[(size_t)(row0 + warp_m * 64 + mi * 16) * K_FEAT +
                    (col0 + warp_n * 64 + ni * 16)],
                acc[mi][ni], K_FEAT, wmma::mem_row_major);
}

// ---------------------------------------------------------------------------
// 5. Epilogue: out = (1/3) X + (2/3) (dinv_i * sum(Ypart) + dd_i * X)
// ---------------------------------------------------------------------------
__global__ void epilogue_kernel(const float* __restrict__ X, float* __restrict__ out) {
    const float REG = 2.0f / 3.0f;
    int idx = blockIdx.x * 256 + threadIdx.x;
    int i = idx >> 9;
    float x = X[idx];
    float y = __half2float(g_Ypart[0][idx]) + __half2float(g_Ypart[1][idx])
            + __half2float(g_Ypart[2][idx]) + __half2float(g_Ypart[3][idx]);
    out[idx] = (1.0f - REG) * x + REG * (g_dinv[i] * y + g_dd[i] * x);
}

// ---------------------------------------------------------------------------
extern "C" void kernel_launch(void* const* d_in, const int* in_sizes, int n_in,
                              void* d_out, int out_size) {
    const float* X = (const float*)d_in[0];
    float* out = (float*)d_out;

    cudaFuncSetAttribute(gemm1_fused_kernel,
                         cudaFuncAttributeMaxDynamicSharedMemorySize, G1_SMEM);
    cudaFuncSetAttribute(gemm2_kernel,
                         cudaFuncAttributeMaxDynamicSharedMemorySize, G2_SMEM);

    normalize_kernel<<<N_ROWS, 128>>>(X);

    gemm1_fused_kernel<<<2080, 256, G1_SMEM>>>();   // triangular grid

    scale_kernel<<<N_ROWS, 128>>>(X);

    dim3 g2(K_FEAT / BN, N_ROWS / BM, NSPLIT);   // 4 x 64 x 4 = 1024 CTAs
    gemm2_kernel<<<g2, 128, G2_SMEM>>>();

    epilogue_kernel<<<(N_ROWS * K_FEAT) / 256, 256>>>(X, out);
}